// round 4
// baseline (speedup 1.0000x reference)
#include <cuda_runtime.h>
#include <cstdint>

// FullTensorProduct, N=4096 rows, MUL=64.
// Per row: a0=in1[:64], a1=in1[64:256] as (64,3); b0,b1 from in2.
// out row (45056 floats):
//   [0,4096)      c000[u*64+v]        = a0[u]*b0[v]
//   [4096,8192)   c110[u*64+v]        = dot(a1[u],b1[v]) / sqrt(3)
//   [8192,20480)  c011[(u*64+v)*3+j]  = a0[u]*b1[v][j]
//   [20480,32768) c101[(u*64+v)*3+i]  = a1[u][i]*b0[v]
//   [32768,45056) c111[(u*64+v)*3+k]  = cross(a1[u],b1[v])[k] / sqrt(2)
//
// R4: 14 output-contiguous pieces per row (2x16KB + 12x12KB), ring of 4x16KB
// smem buffers drained by 1-D TMA bulk stores. 3 CTAs/SM, up to 3 bulk groups
// outstanding per CTA -> smoother DRAM write stream than R3's 2x45KB scheme.

constexpr int ROW_IN  = 256;
constexpr int ROW_OUT = 45056;
constexpr int PIECE_MAX_FLOATS = 4096;           // 16 KB
constexpr int NBUF = 4;
constexpr float INV_SQRT3 = 0.57735026918962576451f;
constexpr float INV_SQRT2 = 0.70710678118654752440f;

__device__ __forceinline__ uint32_t smem_u32(const void* p) {
    uint32_t r;
    asm("{ .reg .u64 t; cvta.to.shared.u64 t, %1; cvt.u32.u64 %0, t; }"
        : "=r"(r) : "l"(p));
    return r;
}

__device__ __forceinline__ void bulk_store(void* gptr, uint32_t saddr, uint32_t bytes) {
    asm volatile(
        "cp.async.bulk.global.shared::cta.bulk_group [%0], [%1], %2;"
        :: "l"(gptr), "r"(saddr), "r"(bytes) : "memory");
}

// Piece table: float offset within row, float count.
// p=0: c000 (4096) | p=1: c110 (4096) | p=2..5: c011 quarters (3072 each)
// p=6..9: c101 quarters | p=10..13: c111 quarters
__device__ __constant__ int P_OFF[14] = {
    0, 4096,
    8192, 11264, 14336, 17408,
    20480, 23552, 26624, 29696,
    32768, 35840, 38912, 41984
};

__global__ __launch_bounds__(256, 3)
void ftp_kernel(const float* __restrict__ in1,
                const float* __restrict__ in2,
                float* __restrict__ out)
{
    __shared__ __align__(16) float a0[64], b0[64];
    __shared__ __align__(16) float a1x[64], a1y[64], a1z[64];
    __shared__ __align__(16) float b1x[64], b1y[64], b1z[64];
    extern __shared__ __align__(16) float buf[];   // NBUF * PIECE_MAX_FLOATS

    const int row = blockIdx.x;
    const int t   = threadIdx.x;

    // Stage inputs: 256 floats per operand, split a1/b1 into x/y/z planes.
    {
        const float v1 = in1[(size_t)row * ROW_IN + t];
        const float v2 = in2[(size_t)row * ROW_IN + t];
        if (t < 64) {
            a0[t] = v1; b0[t] = v2;
        } else {
            int idx = t - 64;
            int u = idx / 3;
            int c = idx - 3 * u;
            if (c == 0)      { a1x[u] = v1; b1x[u] = v2; }
            else if (c == 1) { a1y[u] = v1; b1y[u] = v2; }
            else             { a1z[u] = v1; b1z[u] = v2; }
        }
    }
    __syncthreads();

    // b-side quads for the triple sections: s = t & 15, fixed across pieces.
    const int s = t & 15;
    const float4 b  = ((const float4*)b0)[s];
    const float4 bx = ((const float4*)b1x)[s];
    const float4 by = ((const float4*)b1y)[s];
    const float4 bz = ((const float4*)b1z)[s];

    float* orow = out + (size_t)row * ROW_OUT;

    #pragma unroll
    for (int p = 0; p < 14; ++p) {
        float* B = buf + (p & (NBUF - 1)) * PIECE_MAX_FLOATS;
        float4* B4 = (float4*)B;

        if (p >= NBUF) {
            // Ring reuse: ensure the bulk group that read this buffer is done.
            if (t == 0)
                asm volatile("cp.async.bulk.wait_group.read %0;" :: "n"(NBUF - 1) : "memory");
            __syncthreads();
        }

        if (p == 0) {
            // c000: thread t -> floats [16t,16t+16): u = t>>2, v quads (t&3)*4+j
            const float a = a0[t >> 2];
            const int qv = (t & 3) * 4;
            #pragma unroll
            for (int j = 0; j < 4; ++j) {
                const float4 bq = ((const float4*)b0)[qv + j];
                B4[4 * t + j] = make_float4(a * bq.x, a * bq.y, a * bq.z, a * bq.w);
            }
        } else if (p == 1) {
            // c110: dot(a1[u], b1[v]) / sqrt(3)
            const int u = t >> 2;
            const float ax = a1x[u], ay = a1y[u], az = a1z[u];
            const int qv = (t & 3) * 4;
            #pragma unroll
            for (int j = 0; j < 4; ++j) {
                const float4 qx = ((const float4*)b1x)[qv + j];
                const float4 qy = ((const float4*)b1y)[qv + j];
                const float4 qz = ((const float4*)b1z)[qv + j];
                float4 r;
                r.x = (ax * qx.x + ay * qy.x + az * qz.x) * INV_SQRT3;
                r.y = (ax * qx.y + ay * qy.y + az * qz.y) * INV_SQRT3;
                r.z = (ax * qx.z + ay * qy.z + az * qz.z) * INV_SQRT3;
                r.w = (ax * qx.w + ay * qy.w + az * qz.w) * INV_SQRT3;
                B4[4 * t + j] = r;
            }
        } else {
            // Triple sections: piece quarter q, u = 16q + (t>>4), 4 uv pairs/thread.
            const int sect = (p - 2) >> 2;       // 0=c011, 1=c101, 2=c111
            const int q    = (p - 2) & 3;
            const int u    = (q << 4) + (t >> 4);

            if (sect == 0) {
                const float a = a0[u];
                B4[3*t + 0] = make_float4(a*bx.x, a*by.x, a*bz.x, a*bx.y);
                B4[3*t + 1] = make_float4(a*by.y, a*bz.y, a*bx.z, a*by.z);
                B4[3*t + 2] = make_float4(a*bz.z, a*bx.w, a*by.w, a*bz.w);
            } else if (sect == 1) {
                const float ax = a1x[u], ay = a1y[u], az = a1z[u];
                B4[3*t + 0] = make_float4(ax*b.x, ay*b.x, az*b.x, ax*b.y);
                B4[3*t + 1] = make_float4(ay*b.y, az*b.y, ax*b.z, ay*b.z);
                B4[3*t + 2] = make_float4(az*b.z, ax*b.w, ay*b.w, az*b.w);
            } else {
                const float ax = a1x[u], ay = a1y[u], az = a1z[u];
                const float cx0 = (ay*bz.x - az*by.x) * INV_SQRT2;
                const float cy0 = (az*bx.x - ax*bz.x) * INV_SQRT2;
                const float cz0 = (ax*by.x - ay*bx.x) * INV_SQRT2;
                const float cx1 = (ay*bz.y - az*by.y) * INV_SQRT2;
                const float cy1 = (az*bx.y - ax*bz.y) * INV_SQRT2;
                const float cz1 = (ax*by.y - ay*bx.y) * INV_SQRT2;
                const float cx2 = (ay*bz.z - az*by.z) * INV_SQRT2;
                const float cy2 = (az*bx.z - ax*bz.z) * INV_SQRT2;
                const float cz2 = (ax*by.z - ay*bx.z) * INV_SQRT2;
                const float cx3 = (ay*bz.w - az*by.w) * INV_SQRT2;
                const float cy3 = (az*bx.w - ax*bz.w) * INV_SQRT2;
                const float cz3 = (ax*by.w - ay*bx.w) * INV_SQRT2;
                B4[3*t + 0] = make_float4(cx0, cy0, cz0, cx1);
                B4[3*t + 1] = make_float4(cy1, cz1, cx2, cy2);
                B4[3*t + 2] = make_float4(cz2, cx3, cy3, cz3);
            }
        }

        __syncthreads();

        if (t == 0) {
            asm volatile("fence.proxy.async.shared::cta;" ::: "memory");
            const int bytes = (p < 2) ? 16384 : 12288;
            bulk_store(orow + P_OFF[p], smem_u32(B), bytes);
            asm volatile("cp.async.bulk.commit_group;" ::: "memory");
        }
    }

    // Drain: smem must not be reallocated while TMA still reads it.
    if (t == 0)
        asm volatile("cp.async.bulk.wait_group.read 0;" ::: "memory");
}

extern "C" void kernel_launch(void* const* d_in, const int* in_sizes, int n_in,
                              void* d_out, int out_size)
{
    const float* in1 = (const float*)d_in[0];
    const float* in2 = (const float*)d_in[1];
    float* out = (float*)d_out;
    const int N = in_sizes[0] / ROW_IN;   // 4096 rows

    const int dyn_smem = NBUF * PIECE_MAX_FLOATS * (int)sizeof(float);  // 65536 B
    cudaFuncSetAttribute(ftp_kernel, cudaFuncAttributeMaxDynamicSharedMemorySize, dyn_smem);
    ftp_kernel<<<N, 256, dyn_smem>>>(in1, in2, out);
}